// round 2
// baseline (speedup 1.0000x reference)
#include <cuda_runtime.h>
#include <cuda_bf16.h>
#include <cstddef>

// ---------------------------------------------------------------------------
// Problem constants
// ---------------------------------------------------------------------------
#define B_SZ   2
#define S_SZ   4096
#define HID    2048
#define NH     32
#define HD     64
#define NHD    2048
#define M_ROWS (B_SZ * S_SZ)       // 8192
#define NT     32
#define NKV    4
#define SCALE_F 0.125f

typedef unsigned long long u64;

// ---------------------------------------------------------------------------
// Packed f32x2 primitives (sm_103a FFMA2 path; ptxas never auto-emits these)
// ---------------------------------------------------------------------------
__device__ __forceinline__ u64 pk2(float x, float y) {
    u64 r; asm("mov.b64 %0, {%1, %2};" : "=l"(r) : "f"(x), "f"(y)); return r;
}
__device__ __forceinline__ float2 up2(u64 v) {
    float2 f; asm("mov.b64 {%0, %1}, %2;" : "=f"(f.x), "=f"(f.y) : "l"(v)); return f;
}
__device__ __forceinline__ void ffma2(u64 &d, u64 a, u64 b) {
    asm("fma.rn.f32x2 %0, %1, %2, %0;" : "+l"(d) : "l"(a), "l"(b));
}
__device__ __forceinline__ u64 fmul2(u64 a, u64 b) {
    u64 d; asm("mul.rn.f32x2 %0, %1, %2;" : "=l"(d) : "l"(a), "l"(b)); return d;
}

// ---------------------------------------------------------------------------
// Scratch (device globals: allocation-free rule)
// ---------------------------------------------------------------------------
__device__ float g_q[M_ROWS * NHD];
__device__ float g_k[M_ROWS * NHD];
__device__ float g_v[M_ROWS * NHD];
__device__ float g_att[M_ROWS * NHD];

// ---------------------------------------------------------------------------
// SGEMM: C[M,N] = A[M,K] @ B[K,N], fp32, FFMA2 microtile.
// 128x128 block, BK=8, 256 threads, 8x8 per-thread microtile (4+4 split).
// Accumulators are 32 packed f32x2 (pairs along j). B pairs load pre-packed
// from smem (contiguous); A broadcast packed with mov.b64 (alu pipe).
// ---------------------------------------------------------------------------
__device__ __forceinline__ void gemm_body(
    const float* __restrict__ A, const float* __restrict__ B,
    float* __restrict__ C, int M, int N, int K)
{
    __shared__ float As[2][8][128];
    __shared__ float Bs[2][8][128];

    const int tid = threadIdx.x;
    const int bx = blockIdx.x, by = blockIdx.y;

    const int arow = tid >> 1, acol = (tid & 1) * 4;
    const int brow = tid >> 5, bcol = (tid & 31) * 4;
    const int tr4  = (tid >> 4) * 4, tc4 = (tid & 15) * 4;

    const float* Ag = A + (size_t)(by * 128 + arow) * K + acol;
    const float* Bg = B + (size_t)brow * N + bx * 128 + bcol;

    u64 acc2[8][4];
#pragma unroll
    for (int i = 0; i < 8; i++)
#pragma unroll
        for (int j = 0; j < 4; j++) acc2[i][j] = 0ull;

    float4 a4 = *(const float4*)(Ag);
    float4 b4 = *(const float4*)(Bg);
    As[0][acol + 0][arow] = a4.x;
    As[0][acol + 1][arow] = a4.y;
    As[0][acol + 2][arow] = a4.z;
    As[0][acol + 3][arow] = a4.w;
    *(float4*)&Bs[0][brow][bcol] = b4;
    __syncthreads();

    const int nk = K >> 3;
    for (int t = 0; t < nk; ++t) {
        const int cur = t & 1;
        if (t + 1 < nk) {
            a4 = *(const float4*)(Ag + (t + 1) * 8);
            b4 = *(const float4*)(Bg + (size_t)(t + 1) * 8 * N);
        }
#pragma unroll
        for (int k = 0; k < 8; ++k) {
            float ar[8];
            *(float4*)(ar)     = *(const float4*)&As[cur][k][tr4];
            *(float4*)(ar + 4) = *(const float4*)&As[cur][k][tr4 + 64];
            const ulonglong2 bl = *(const ulonglong2*)&Bs[cur][k][tc4];
            const ulonglong2 bh = *(const ulonglong2*)&Bs[cur][k][tc4 + 64];
            u64 b2[4] = { bl.x, bl.y, bh.x, bh.y };
            u64 a2[8];
#pragma unroll
            for (int i = 0; i < 8; i++) a2[i] = pk2(ar[i], ar[i]);
#pragma unroll
            for (int i = 0; i < 8; i++)
#pragma unroll
                for (int j = 0; j < 4; j++)
                    ffma2(acc2[i][j], a2[i], b2[j]);
        }
        if (t + 1 < nk) {
            const int nxt = cur ^ 1;
            As[nxt][acol + 0][arow] = a4.x;
            As[nxt][acol + 1][arow] = a4.y;
            As[nxt][acol + 2][arow] = a4.z;
            As[nxt][acol + 3][arow] = a4.w;
            *(float4*)&Bs[nxt][brow][bcol] = b4;
        }
        __syncthreads();
    }

#pragma unroll
    for (int i = 0; i < 8; i++) {
        const int row = by * 128 + ((i < 4) ? (tr4 + i) : (64 + tr4 + (i - 4)));
        float* Cr = C + (size_t)row * N + bx * 128;
        const float2 c0 = up2(acc2[i][0]), c1 = up2(acc2[i][1]);
        const float2 c2 = up2(acc2[i][2]), c3 = up2(acc2[i][3]);
        *(float4*)(Cr + tc4)      = make_float4(c0.x, c0.y, c1.x, c1.y);
        *(float4*)(Cr + tc4 + 64) = make_float4(c2.x, c2.y, c3.x, c3.y);
    }
}

__global__ __launch_bounds__(256, 2) void qkv_kernel(
    const float* __restrict__ A,
    const float* __restrict__ W0, const float* __restrict__ W1, const float* __restrict__ W2,
    float* __restrict__ C0, float* __restrict__ C1, float* __restrict__ C2)
{
    const float* W = (blockIdx.z == 0) ? W0 : (blockIdx.z == 1) ? W1 : W2;
    float*       C = (blockIdx.z == 0) ? C0 : (blockIdx.z == 1) ? C1 : C2;
    gemm_body(A, W, C, M_ROWS, NHD, HID);
}

__global__ __launch_bounds__(256, 2) void gemm_kernel(
    const float* __restrict__ A, const float* __restrict__ B, float* __restrict__ C,
    int M, int N, int K)
{
    gemm_body(A, B, C, M, N, K);
}

// ---------------------------------------------------------------------------
// Block-sparse tiled attention (FFMA2 QK + PV).
// ---------------------------------------------------------------------------
#define ATT_SMEM_FLOATS (128 * 64 * 2 + 128 * 129 + 256)
#define ATT_SMEM_BYTES  (ATT_SMEM_FLOATS * 4)

__device__ __forceinline__ int token_of(int tile, int jj)
{
    return ((tile >> 2) << 9) + ((jj >> 4) << 6) + ((tile & 3) << 4) + (jj & 15);
}

__global__ __launch_bounds__(256) void attn_kernel(
    const float* __restrict__ Q, const float* __restrict__ Kb,
    const float* __restrict__ Vb, float* __restrict__ O)
{
    extern __shared__ float sm[];
    float* Ks = sm;                       // [128][64]
    float* Vs = sm + 128 * 64;            // [128][64]
    float* Ss = sm + 2 * 128 * 64;        // [128][129]
    float* Rm = Ss + 128 * 129;           // [2][128]

    const int t = blockIdx.x, h = blockIdx.y, b = blockIdx.z;
    const int tid = threadIdx.x;
    const int p = tid >> 7, j = tid & 127;

    const int tr = t >> 2, tc = t & 3;
    const int cr = min(max(tr, 1), 7);
    const int cc = min(max(tc, 1), 3);
    int kts[NKV];
    kts[0] = (cr - 1) * 4 + (cc - 1);
    kts[1] = (cr - 1) * 4 + cc;
    kts[2] = cr * 4 + (cc - 1);
    kts[3] = cr * 4 + cc;

    const size_t base = (size_t)b * S_SZ * NHD + (size_t)h * HD;

    // Query row, pre-packed as 32 f32x2 pairs.
    const int qs = token_of(t, j);
    const float* qrow = Q + base + (size_t)qs * NHD;
    u64 qp[32];
#pragma unroll
    for (int i = 0; i < 16; i++) {
        const ulonglong2 qq = *(const ulonglong2*)(qrow + i * 4);
        qp[i * 2]     = qq.x;
        qp[i * 2 + 1] = qq.y;
    }

    float m = -1e30f, l = 0.f;
    u64 o2[16];
#pragma unroll
    for (int d = 0; d < 16; d++) o2[d] = 0ull;

    for (int w = 0; w < NKV; ++w) {
        const int kt = kts[w];
        __syncthreads();
        for (int idx = tid; idx < 128 * 16; idx += 256) {
            const int row = idx >> 4, c4 = (idx & 15) * 4;
            const int ks = token_of(kt, row);
            const size_t off = base + (size_t)ks * NHD + c4;
            *(float4*)&Ks[row * 64 + c4] = *(const float4*)(Kb + off);
            *(float4*)&Vs[row * 64 + c4] = *(const float4*)(Vb + off);
        }
        __syncthreads();

        // QK: packed dual-lane dot products.
        float tmax = -1e30f;
        for (int kk = 0; kk < 64; ++kk) {
            const int key = p * 64 + kk;
            const ulonglong2* kr2 = (const ulonglong2*)&Ks[key * 64];
            u64 s01 = 0ull, s23 = 0ull;
#pragma unroll
            for (int i = 0; i < 16; i++) {
                const ulonglong2 k2v = kr2[i];
                ffma2(s01, qp[i * 2],     k2v.x);
                ffma2(s23, qp[i * 2 + 1], k2v.y);
            }
            const float2 f0 = up2(s01), f1 = up2(s23);
            const float s = ((f0.x + f0.y) + (f1.x + f1.y)) * SCALE_F;
            Ss[j * 129 + key] = s;
            tmax = fmaxf(tmax, s);
        }
        Rm[p * 128 + j] = tmax;
        __syncthreads();

        const float mt = fmaxf(Rm[j], Rm[128 + j]);
        const float mnew = fmaxf(m, mt);
        const float alpha = __expf(m - mnew);
        m = mnew;
        l *= alpha;
        const u64 al2 = pk2(alpha, alpha);
#pragma unroll
        for (int d = 0; d < 16; d++) o2[d] = fmul2(o2[d], al2);

        // PV: e broadcast packed once; V pairs pre-packed from smem.
        float lsum = 0.f;
        const float* vbp = &Vs[p * 32];
        for (int k2 = 0; k2 < 128; ++k2) {
            const float e = __expf(Ss[j * 129 + k2] - m);
            lsum += e;
            const u64 e2 = pk2(e, e);
            const ulonglong2* vr2 = (const ulonglong2*)(vbp + k2 * 64);
#pragma unroll
            for (int d2 = 0; d2 < 8; d2++) {
                const ulonglong2 vv = vr2[d2];
                ffma2(o2[d2 * 2],     e2, vv.x);
                ffma2(o2[d2 * 2 + 1], e2, vv.y);
            }
        }
        l += lsum;
    }

    const float inv = 1.f / l;
    const u64 inv2 = pk2(inv, inv);
    float* orow = O + base + (size_t)qs * NHD + p * 32;
#pragma unroll
    for (int d2 = 0; d2 < 8; d2++) {
        ulonglong2 st;
        st.x = fmul2(o2[d2 * 2],     inv2);
        st.y = fmul2(o2[d2 * 2 + 1], inv2);
        *(ulonglong2*)(orow + d2 * 4) = st;
    }
}

// ---------------------------------------------------------------------------
// Launch
// ---------------------------------------------------------------------------
extern "C" void kernel_launch(void* const* d_in, const int* in_sizes, int n_in,
                              void* d_out, int out_size)
{
    const float* hs = (const float*)d_in[0];
    const float* Wq = (const float*)d_in[1];
    const float* Wk = (const float*)d_in[2];
    const float* Wv = (const float*)d_in[3];
    const float* Wo = (const float*)d_in[4];
    float* out = (float*)d_out;

    float *q, *k, *v, *att;
    cudaGetSymbolAddress((void**)&q,   g_q);
    cudaGetSymbolAddress((void**)&k,   g_k);
    cudaGetSymbolAddress((void**)&v,   g_v);
    cudaGetSymbolAddress((void**)&att, g_att);

    cudaFuncSetAttribute(attn_kernel, cudaFuncAttributeMaxDynamicSharedMemorySize,
                         ATT_SMEM_BYTES);

    const dim3 tb(256);

    qkv_kernel<<<dim3(NHD / 128, M_ROWS / 128, 3), tb>>>(hs, Wq, Wk, Wv, q, k, v);
    attn_kernel<<<dim3(NT, NH, B_SZ), tb, ATT_SMEM_BYTES>>>(q, k, v, att);
    gemm_kernel<<<dim3(HID / 128, M_ROWS / 128), tb>>>(att, Wo, out, M_ROWS, HID, NHD);
}

// round 4
// speedup vs baseline: 1.5135x; 1.5135x over previous
#include <cuda_runtime.h>
#include <cuda_bf16.h>
#include <cstdint>
#include <cstddef>

// ---------------------------------------------------------------------------
// Problem constants
// ---------------------------------------------------------------------------
#define B_SZ   2
#define S_SZ   4096
#define HID    2048
#define NH     32
#define HD     64
#define NHD    2048
#define M_ROWS (B_SZ * S_SZ)       // 8192
#define NT     32
#define NKV    4
#define SCALE_F 0.125f
#define KDIM   2048

// ---------------------------------------------------------------------------
// PTX helpers (all plain sm_80+ features; no arch-suffix-gated instructions)
// ---------------------------------------------------------------------------
__device__ __forceinline__ uint32_t smem_u32(const void* p) {
    uint32_t a;
    asm("{ .reg .u64 t; cvta.to.shared.u64 t, %1; cvt.u32.u64 %0, t; }" : "=r"(a) : "l"(p));
    return a;
}
#define CP_ASYNC16(dst, src) \
    asm volatile("cp.async.cg.shared.global [%0], [%1], 16;" :: "r"(dst), "l"(src) : "memory")
#define CP_COMMIT()  asm volatile("cp.async.commit_group;" ::: "memory")
#define CP_WAIT(n)   asm volatile("cp.async.wait_group %0;" :: "n"(n) : "memory")

__device__ __forceinline__ void ldm4(uint32_t* r, uint32_t addr) {
    asm volatile("ldmatrix.sync.aligned.m8n8.x4.shared.b16 {%0,%1,%2,%3}, [%4];"
        : "=r"(r[0]), "=r"(r[1]), "=r"(r[2]), "=r"(r[3]) : "r"(addr));
}
__device__ __forceinline__ void mma_bf16(float* d, const uint32_t* a, uint32_t b0, uint32_t b1) {
    asm volatile("mma.sync.aligned.m16n8k16.row.col.f32.bf16.bf16.f32 "
        "{%0,%1,%2,%3}, {%4,%5,%6,%7}, {%8,%9}, {%0,%1,%2,%3};"
        : "+f"(d[0]), "+f"(d[1]), "+f"(d[2]), "+f"(d[3])
        : "r"(a[0]), "r"(a[1]), "r"(a[2]), "r"(a[3]), "r"(b0), "r"(b1));
}

// ---------------------------------------------------------------------------
// Scratch (device globals)
// ---------------------------------------------------------------------------
__device__ float g_q[M_ROWS * NHD];
__device__ float g_k[M_ROWS * NHD];
__device__ float g_v[M_ROWS * NHD];
__device__ __nv_bfloat16 g_hshi[M_ROWS * HID];
__device__ __nv_bfloat16 g_hslo[M_ROWS * HID];
__device__ __nv_bfloat16 g_wthi[4 * HID * NHD];   // [N,K] transposed, 4 weights
__device__ __nv_bfloat16 g_wtlo[4 * HID * NHD];
__device__ __nv_bfloat16 g_atthi[M_ROWS * NHD];
__device__ __nv_bfloat16 g_attlo[M_ROWS * NHD];

// ---------------------------------------------------------------------------
// Pre-pass 1: elementwise fp32 -> (hi, lo) bf16 split
// ---------------------------------------------------------------------------
__global__ void split_kernel(const float* __restrict__ x,
                             __nv_bfloat16* __restrict__ hi,
                             __nv_bfloat16* __restrict__ lo, int n4)
{
    int i = blockIdx.x * blockDim.x + threadIdx.x;
    if (i >= n4) return;
    const float4 v = ((const float4*)x)[i];
    __nv_bfloat16 h0 = __float2bfloat16(v.x), h1 = __float2bfloat16(v.y);
    __nv_bfloat16 h2 = __float2bfloat16(v.z), h3 = __float2bfloat16(v.w);
    __nv_bfloat16 l0 = __float2bfloat16(v.x - __bfloat162float(h0));
    __nv_bfloat16 l1 = __float2bfloat16(v.y - __bfloat162float(h1));
    __nv_bfloat16 l2 = __float2bfloat16(v.z - __bfloat162float(h2));
    __nv_bfloat16 l3 = __float2bfloat16(v.w - __bfloat162float(h3));
    ((__nv_bfloat162*)hi)[i * 2]     = __nv_bfloat162(h0, h1);
    ((__nv_bfloat162*)hi)[i * 2 + 1] = __nv_bfloat162(h2, h3);
    ((__nv_bfloat162*)lo)[i * 2]     = __nv_bfloat162(l0, l1);
    ((__nv_bfloat162*)lo)[i * 2 + 1] = __nv_bfloat162(l2, l3);
}

// ---------------------------------------------------------------------------
// Pre-pass 2: W[K,N] -> Wt[N,K] with bf16 hi/lo split (32x32 smem tiles)
// ---------------------------------------------------------------------------
__global__ void wsplit_kernel(const float* __restrict__ W0, const float* __restrict__ W1,
                              const float* __restrict__ W2, const float* __restrict__ W3,
                              __nv_bfloat16* __restrict__ hi, __nv_bfloat16* __restrict__ lo)
{
    const int z = blockIdx.z;
    const float* W = (z == 0) ? W0 : (z == 1) ? W1 : (z == 2) ? W2 : W3;
    __shared__ float t[32][33];
    const int n0 = blockIdx.x * 32, k0 = blockIdx.y * 32;
    const int tx = threadIdx.x, ty = threadIdx.y;   // 32 x 8
#pragma unroll
    for (int i = 0; i < 4; i++)
        t[ty + 8 * i][tx] = W[(size_t)(k0 + ty + 8 * i) * NHD + n0 + tx];
    __syncthreads();
    const size_t zo = (size_t)z * HID * NHD;
#pragma unroll
    for (int i = 0; i < 4; i++) {
        const float x = t[tx][ty + 8 * i];
        const __nv_bfloat16 h = __float2bfloat16(x);
        const __nv_bfloat16 l = __float2bfloat16(x - __bfloat162float(h));
        const size_t o = zo + (size_t)(n0 + ty + 8 * i) * KDIM + k0 + tx;
        hi[o] = h;
        lo[o] = l;
    }
}

// ---------------------------------------------------------------------------
// Split-bf16 HMMA GEMM: C[M,2048] = A[M,K] @ B[2048,K]^T  (3-product split)
// CTA tile 128x128, BK=32, 8 warps (2m x 4n, warp tile 64x32),
// cp.async double-buffered smem, padded stride 40 bf16 rows (conflict-free
// ldmatrix), mma.sync m16n8k16 bf16 with fp32 accumulators.
// ---------------------------------------------------------------------------
#define BK        32
#define NITER     (KDIM / BK)        // 64
#define STR_E     40                 // padded row stride, elements
#define STR_B     80                 // bytes
#define MAT_B     (128 * STR_B)      // 10240 bytes per matrix
#define STAGE_B   (4 * MAT_B)        // 40960: Ahi, Alo, Bhi, Blo
#define GEMM_SMEM (2 * STAGE_B)      // 81920

struct GemmPtrs {
    const __nv_bfloat16 *Ahi, *Alo, *Bhi, *Blo;
    float* C;
};

__device__ __forceinline__ void gemm_copy_stage(
    uint32_t sdst, const GemmPtrs& g, int m0, int n0, int kb, int tid)
{
#pragma unroll
    for (int i = 0; i < 8; i++) {
        const int idx = tid + i * 256;
        const int mat = idx >> 9, rem = idx & 511;
        const int row = rem >> 2, c = rem & 3;
        const __nv_bfloat16* sp;
        if (mat == 0)      sp = g.Ahi + (size_t)(m0 + row) * KDIM + kb + c * 8;
        else if (mat == 1) sp = g.Alo + (size_t)(m0 + row) * KDIM + kb + c * 8;
        else if (mat == 2) sp = g.Bhi + (size_t)(n0 + row) * KDIM + kb + c * 8;
        else               sp = g.Blo + (size_t)(n0 + row) * KDIM + kb + c * 8;
        CP_ASYNC16(sdst + mat * MAT_B + row * STR_B + c * 16, sp);
    }
    CP_COMMIT();
}

__device__ __forceinline__ void gemm_body_mma(const GemmPtrs& g)
{
    extern __shared__ __align__(128) char smem[];
    const uint32_t sbase = smem_u32(smem);
    const int tid = threadIdx.x, wid = tid >> 5, lane = tid & 31;
    const int m0 = blockIdx.y * 128, n0 = blockIdx.x * 128;
    const int wm = wid & 1, wn = wid >> 1;

    float acc[4][4][4];
#pragma unroll
    for (int a = 0; a < 4; a++)
#pragma unroll
        for (int b = 0; b < 4; b++)
#pragma unroll
            for (int c = 0; c < 4; c++) acc[a][b][c] = 0.f;

    // ldmatrix lane offset: lanes 0-7 rows(+klo), 8-15 rows+8(+klo),
    // 16-23 rows(+khi), 24-31 rows+8(+khi)
    const uint32_t lofs = (uint32_t)((lane & 15) * STR_B + (lane >> 4) * 16);

    gemm_copy_stage(sbase, g, m0, n0, 0, tid);

    for (int t = 0; t < NITER; ++t) {
        if (t + 1 < NITER) {
            gemm_copy_stage(sbase + ((t + 1) & 1) * STAGE_B, g, m0, n0, (t + 1) * BK, tid);
            CP_WAIT(1);
        } else {
            CP_WAIT(0);
        }
        __syncthreads();

        const uint32_t s0 = sbase + (t & 1) * STAGE_B;
#pragma unroll
        for (int ks = 0; ks < 2; ++ks) {
            const uint32_t aoff = s0 + (uint32_t)(wm * 64 * STR_B + ks * 32) + lofs;
            const uint32_t boff = s0 + 2 * MAT_B + (uint32_t)(wn * 32 * STR_B + ks * 32) + lofs;

            uint32_t Ah[16], Bh[8], Bl[8];
            ldm4(Ah + 0,  aoff);
            ldm4(Ah + 4,  aoff + 16 * STR_B);
            ldm4(Ah + 8,  aoff + 32 * STR_B);
            ldm4(Ah + 12, aoff + 48 * STR_B);
            ldm4(Bh + 0, boff);
            ldm4(Bh + 4, boff + 16 * STR_B);
            // hi * hi
#pragma unroll
            for (int mf = 0; mf < 4; mf++)
#pragma unroll
                for (int nf = 0; nf < 4; nf++)
                    mma_bf16(acc[mf][nf], Ah + mf * 4,
                             Bh[(nf >> 1) * 4 + (nf & 1)], Bh[(nf >> 1) * 4 + 2 + (nf & 1)]);
            // hi * lo
            ldm4(Bl + 0, boff + MAT_B);
            ldm4(Bl + 4, boff + MAT_B + 16 * STR_B);
#pragma unroll
            for (int mf = 0; mf < 4; mf++)
#pragma unroll
                for (int nf = 0; nf < 4; nf++)
                    mma_bf16(acc[mf][nf], Ah + mf * 4,
                             Bl[(nf >> 1) * 4 + (nf & 1)], Bl[(nf >> 1) * 4 + 2 + (nf & 1)]);
            // lo * hi (reuse Ah registers)
            ldm4(Ah + 0,  aoff + MAT_B);
            ldm4(Ah + 4,  aoff + MAT_B + 16 * STR_B);
            ldm4(Ah + 8,  aoff + MAT_B + 32 * STR_B);
            ldm4(Ah + 12, aoff + MAT_B + 48 * STR_B);
#pragma unroll
            for (int mf = 0; mf < 4; mf++)
#pragma unroll
                for (int nf = 0; nf < 4; nf++)
                    mma_bf16(acc[mf][nf], Ah + mf * 4,
                             Bh[(nf >> 1) * 4 + (nf & 1)], Bh[(nf >> 1) * 4 + 2 + (nf & 1)]);
        }
        __syncthreads();
    }

    // Epilogue: direct fp32 stores (N = 2048 fixed)
    const int gq = lane >> 2, tig = lane & 3;
#pragma unroll
    for (int mf = 0; mf < 4; mf++) {
        const int row = m0 + wm * 64 + mf * 16 + gq;
#pragma unroll
        for (int nf = 0; nf < 4; nf++) {
            const int col = n0 + wn * 32 + nf * 8 + tig * 2;
            *(float2*)&g.C[(size_t)row * 2048 + col] =
                make_float2(acc[mf][nf][0], acc[mf][nf][1]);
            *(float2*)&g.C[(size_t)(row + 8) * 2048 + col] =
                make_float2(acc[mf][nf][2], acc[mf][nf][3]);
        }
    }
}

__global__ __launch_bounds__(256, 2) void qkv_mma_kernel(
    const __nv_bfloat16* __restrict__ Ahi, const __nv_bfloat16* __restrict__ Alo,
    const __nv_bfloat16* __restrict__ Whi, const __nv_bfloat16* __restrict__ Wlo,
    float* __restrict__ Cq, float* __restrict__ Ck, float* __restrict__ Cv)
{
    const size_t WSZ = (size_t)HID * NHD;
    const int z = blockIdx.z;
    GemmPtrs g;
    g.Ahi = Ahi; g.Alo = Alo;
    g.Bhi = Whi + (size_t)z * WSZ; g.Blo = Wlo + (size_t)z * WSZ;
    g.C = (z == 0) ? Cq : (z == 1) ? Ck : Cv;
    gemm_body_mma(g);
}

__global__ __launch_bounds__(256, 2) void out_mma_kernel(
    const __nv_bfloat16* __restrict__ Ahi, const __nv_bfloat16* __restrict__ Alo,
    const __nv_bfloat16* __restrict__ Whi, const __nv_bfloat16* __restrict__ Wlo,
    float* __restrict__ C)
{
    GemmPtrs g;
    g.Ahi = Ahi; g.Alo = Alo; g.Bhi = Whi; g.Blo = Wlo; g.C = C;
    gemm_body_mma(g);
}

// ---------------------------------------------------------------------------
// Block-sparse tiled attention (fp32 SIMT), writes split-bf16 output
// ---------------------------------------------------------------------------
#define ATT_SMEM_FLOATS (128 * 64 * 2 + 128 * 129 + 256)
#define ATT_SMEM_BYTES  (ATT_SMEM_FLOATS * 4)

__device__ __forceinline__ int token_of(int tile, int jj)
{
    return ((tile >> 2) << 9) + ((jj >> 4) << 6) + ((tile & 3) << 4) + (jj & 15);
}

__global__ __launch_bounds__(256) void attn_kernel(
    const float* __restrict__ Q, const float* __restrict__ Kb,
    const float* __restrict__ Vb,
    __nv_bfloat16* __restrict__ Ohi, __nv_bfloat16* __restrict__ Olo)
{
    extern __shared__ float sm[];
    float* Ks = sm;
    float* Vs = sm + 128 * 64;
    float* Ss = sm + 2 * 128 * 64;
    float* Rm = Ss + 128 * 129;

    const int t = blockIdx.x, h = blockIdx.y, b = blockIdx.z;
    const int tid = threadIdx.x;
    const int p = tid >> 7, j = tid & 127;

    const int tr = t >> 2, tc = t & 3;
    const int cr = min(max(tr, 1), 7);
    const int cc = min(max(tc, 1), 3);
    int kts[NKV];
    kts[0] = (cr - 1) * 4 + (cc - 1);
    kts[1] = (cr - 1) * 4 + cc;
    kts[2] = cr * 4 + (cc - 1);
    kts[3] = cr * 4 + cc;

    const size_t base = (size_t)b * S_SZ * NHD + (size_t)h * HD;

    const int qs = token_of(t, j);
    const float* qrow = Q + base + (size_t)qs * NHD;
    float4 qv[16];
#pragma unroll
    for (int i = 0; i < 16; i++) qv[i] = *(const float4*)(qrow + i * 4);

    float m = -1e30f, l = 0.f;
    float o[32];
#pragma unroll
    for (int d = 0; d < 32; d++) o[d] = 0.f;

    for (int w = 0; w < NKV; ++w) {
        const int kt = kts[w];
        __syncthreads();
        for (int idx = tid; idx < 128 * 16; idx += 256) {
            const int row = idx >> 4, c4 = (idx & 15) * 4;
            const int ks = token_of(kt, row);
            const size_t off = base + (size_t)ks * NHD + c4;
            *(float4*)&Ks[row * 64 + c4] = *(const float4*)(Kb + off);
            *(float4*)&Vs[row * 64 + c4] = *(const float4*)(Vb + off);
        }
        __syncthreads();

        float tmax = -1e30f;
        for (int kk = 0; kk < 64; ++kk) {
            const int key = p * 64 + kk;
            const float* kr = &Ks[key * 64];
            float s0 = 0.f, s1 = 0.f, s2 = 0.f, s3 = 0.f;
#pragma unroll
            for (int i = 0; i < 16; i++) {
                const float4 k4 = *(const float4*)(kr + i * 4);
                s0 = fmaf(qv[i].x, k4.x, s0);
                s1 = fmaf(qv[i].y, k4.y, s1);
                s2 = fmaf(qv[i].z, k4.z, s2);
                s3 = fmaf(qv[i].w, k4.w, s3);
            }
            float s = ((s0 + s1) + (s2 + s3)) * SCALE_F;
            Ss[j * 129 + key] = s;
            tmax = fmaxf(tmax, s);
        }
        Rm[p * 128 + j] = tmax;
        __syncthreads();

        const float mt = fmaxf(Rm[j], Rm[128 + j]);
        const float mnew = fmaxf(m, mt);
        const float alpha = __expf(m - mnew);
        m = mnew;
        l *= alpha;
#pragma unroll
        for (int d = 0; d < 32; d++) o[d] *= alpha;

        float lsum = 0.f;
        const float* vbp = &Vs[p * 32];
        for (int k2 = 0; k2 < 128; ++k2) {
            const float e = __expf(Ss[j * 129 + k2] - m);
            lsum += e;
            const float* vr = vbp + k2 * 64;
#pragma unroll
            for (int d4 = 0; d4 < 8; d4++) {
                const float4 v4 = *(const float4*)(vr + d4 * 4);
                o[d4 * 4 + 0] = fmaf(e, v4.x, o[d4 * 4 + 0]);
                o[d4 * 4 + 1] = fmaf(e, v4.y, o[d4 * 4 + 1]);
                o[d4 * 4 + 2] = fmaf(e, v4.z, o[d4 * 4 + 2]);
                o[d4 * 4 + 3] = fmaf(e, v4.w, o[d4 * 4 + 3]);
            }
        }
        l += lsum;
    }

    const float inv = 1.f / l;
    const size_t orow = base + (size_t)qs * NHD + p * 32;
#pragma unroll
    for (int d2 = 0; d2 < 16; d2++) {
        const float x0 = o[d2 * 2] * inv, x1 = o[d2 * 2 + 1] * inv;
        const __nv_bfloat16 h0 = __float2bfloat16(x0), h1 = __float2bfloat16(x1);
        const __nv_bfloat16 l0 = __float2bfloat16(x0 - __bfloat162float(h0));
        const __nv_bfloat16 l1 = __float2bfloat16(x1 - __bfloat162float(h1));
        *(__nv_bfloat162*)(Ohi + orow + d2 * 2) = __nv_bfloat162(h0, h1);
        *(__nv_bfloat162*)(Olo + orow + d2 * 2) = __nv_bfloat162(l0, l1);
    }
}

// ---------------------------------------------------------------------------
// Launch
// ---------------------------------------------------------------------------
extern "C" void kernel_launch(void* const* d_in, const int* in_sizes, int n_in,
                              void* d_out, int out_size)
{
    const float* hs = (const float*)d_in[0];
    const float* Wq = (const float*)d_in[1];
    const float* Wk = (const float*)d_in[2];
    const float* Wv = (const float*)d_in[3];
    const float* Wo = (const float*)d_in[4];
    float* out = (float*)d_out;

    float *q, *k, *v;
    __nv_bfloat16 *hshi, *hslo, *wthi, *wtlo, *atthi, *attlo;
    cudaGetSymbolAddress((void**)&q, g_q);
    cudaGetSymbolAddress((void**)&k, g_k);
    cudaGetSymbolAddress((void**)&v, g_v);
    cudaGetSymbolAddress((void**)&hshi, g_hshi);
    cudaGetSymbolAddress((void**)&hslo, g_hslo);
    cudaGetSymbolAddress((void**)&wthi, g_wthi);
    cudaGetSymbolAddress((void**)&wtlo, g_wtlo);
    cudaGetSymbolAddress((void**)&atthi, g_atthi);
    cudaGetSymbolAddress((void**)&attlo, g_attlo);

    cudaFuncSetAttribute(qkv_mma_kernel, cudaFuncAttributeMaxDynamicSharedMemorySize, GEMM_SMEM);
    cudaFuncSetAttribute(out_mma_kernel, cudaFuncAttributeMaxDynamicSharedMemorySize, GEMM_SMEM);
    cudaFuncSetAttribute(attn_kernel, cudaFuncAttributeMaxDynamicSharedMemorySize, ATT_SMEM_BYTES);

    // Pre-pass: split HS; transpose+split the 4 weights to [N,K] bf16 hi/lo.
    const int n4 = (M_ROWS * HID) / 4;
    split_kernel<<<(n4 + 255) / 256, 256>>>(hs, hshi, hslo, n4);
    wsplit_kernel<<<dim3(NHD / 32, HID / 32, 4), dim3(32, 8)>>>(Wq, Wk, Wv, Wo, wthi, wtlo);

    // QKV projections (HMMA split-bf16), fused over z to reuse A via L2
    qkv_mma_kernel<<<dim3(NHD / 128, M_ROWS / 128, 3), 256, GEMM_SMEM>>>(
        hshi, hslo, wthi, wtlo, q, k, v);

    // Attention (fp32), writes split-bf16 output for the Wo GEMM
    attn_kernel<<<dim3(NT, NH, B_SZ), 256, ATT_SMEM_BYTES>>>(q, k, v, atthi, attlo);

    // Output projection (weight index 3)
    const size_t WSZ = (size_t)HID * NHD;
    out_mma_kernel<<<dim3(HID / 128, M_ROWS / 128), 256, GEMM_SMEM>>>(
        atthi, attlo, wthi + 3 * WSZ, wtlo + 3 * WSZ, out);
}

// round 5
// speedup vs baseline: 2.1420x; 1.4152x over previous
#include <cuda_runtime.h>
#include <cuda_bf16.h>
#include <cstdint>
#include <cstddef>

// ---------------------------------------------------------------------------
// Problem constants
// ---------------------------------------------------------------------------
#define B_SZ   2
#define S_SZ   4096
#define HID    2048
#define NH     32
#define HD     64
#define NHD    2048
#define M_ROWS (B_SZ * S_SZ)       // 8192
#define NT     32
#define NKV    4
#define SCALE_F 0.125f
#define KDIM   2048

// ---------------------------------------------------------------------------
// PTX helpers (plain sm_80+ features only)
// ---------------------------------------------------------------------------
__device__ __forceinline__ uint32_t smem_u32(const void* p) {
    uint32_t a;
    asm("{ .reg .u64 t; cvta.to.shared.u64 t, %1; cvt.u32.u64 %0, t; }" : "=r"(a) : "l"(p));
    return a;
}
#define CP_ASYNC16(dst, src) \
    asm volatile("cp.async.cg.shared.global [%0], [%1], 16;" :: "r"(dst), "l"(src) : "memory")
#define CP_COMMIT()  asm volatile("cp.async.commit_group;" ::: "memory")
#define CP_WAIT(n)   asm volatile("cp.async.wait_group %0;" :: "n"(n) : "memory")

__device__ __forceinline__ void ldm4(uint32_t* r, uint32_t addr) {
    asm volatile("ldmatrix.sync.aligned.m8n8.x4.shared.b16 {%0,%1,%2,%3}, [%4];"
        : "=r"(r[0]), "=r"(r[1]), "=r"(r[2]), "=r"(r[3]) : "r"(addr));
}
__device__ __forceinline__ void ldm4t(uint32_t* r, uint32_t addr) {
    asm volatile("ldmatrix.sync.aligned.m8n8.x4.trans.shared.b16 {%0,%1,%2,%3}, [%4];"
        : "=r"(r[0]), "=r"(r[1]), "=r"(r[2]), "=r"(r[3]) : "r"(addr));
}
__device__ __forceinline__ void mma_bf16(float* d, const uint32_t* a, uint32_t b0, uint32_t b1) {
    asm volatile("mma.sync.aligned.m16n8k16.row.col.f32.bf16.bf16.f32 "
        "{%0,%1,%2,%3}, {%4,%5,%6,%7}, {%8,%9}, {%0,%1,%2,%3};"
        : "+f"(d[0]), "+f"(d[1]), "+f"(d[2]), "+f"(d[3])
        : "r"(a[0]), "r"(a[1]), "r"(a[2]), "r"(a[3]), "r"(b0), "r"(b1));
}
__device__ __forceinline__ uint32_t pkbf(float a, float b) {
    __nv_bfloat162 t(__float2bfloat16(a), __float2bfloat16(b));
    return *(uint32_t*)&t;
}

// ---------------------------------------------------------------------------
// Scratch (device globals)
// ---------------------------------------------------------------------------
__device__ __nv_bfloat16 g_hshi[M_ROWS * HID];
__device__ __nv_bfloat16 g_hslo[M_ROWS * HID];
__device__ __nv_bfloat16 g_wthi[4 * HID * NHD];   // [N,K] transposed, 4 weights
__device__ __nv_bfloat16 g_wtlo[4 * HID * NHD];
__device__ __nv_bfloat16 g_qhi[M_ROWS * NHD];
__device__ __nv_bfloat16 g_qlo[M_ROWS * NHD];
__device__ __nv_bfloat16 g_khi[M_ROWS * NHD];
__device__ __nv_bfloat16 g_klo[M_ROWS * NHD];
__device__ __nv_bfloat16 g_vhi[M_ROWS * NHD];
__device__ __nv_bfloat16 g_vlo[M_ROWS * NHD];
__device__ __nv_bfloat16 g_atthi[M_ROWS * NHD];
__device__ __nv_bfloat16 g_attlo[M_ROWS * NHD];

// ---------------------------------------------------------------------------
// Pre-pass 1: elementwise fp32 -> (hi, lo) bf16 split
// ---------------------------------------------------------------------------
__global__ void split_kernel(const float* __restrict__ x,
                             __nv_bfloat16* __restrict__ hi,
                             __nv_bfloat16* __restrict__ lo, int n4)
{
    int i = blockIdx.x * blockDim.x + threadIdx.x;
    if (i >= n4) return;
    const float4 v = ((const float4*)x)[i];
    __nv_bfloat16 h0 = __float2bfloat16(v.x), h1 = __float2bfloat16(v.y);
    __nv_bfloat16 h2 = __float2bfloat16(v.z), h3 = __float2bfloat16(v.w);
    __nv_bfloat16 l0 = __float2bfloat16(v.x - __bfloat162float(h0));
    __nv_bfloat16 l1 = __float2bfloat16(v.y - __bfloat162float(h1));
    __nv_bfloat16 l2 = __float2bfloat16(v.z - __bfloat162float(h2));
    __nv_bfloat16 l3 = __float2bfloat16(v.w - __bfloat162float(h3));
    ((__nv_bfloat162*)hi)[i * 2]     = __nv_bfloat162(h0, h1);
    ((__nv_bfloat162*)hi)[i * 2 + 1] = __nv_bfloat162(h2, h3);
    ((__nv_bfloat162*)lo)[i * 2]     = __nv_bfloat162(l0, l1);
    ((__nv_bfloat162*)lo)[i * 2 + 1] = __nv_bfloat162(l2, l3);
}

// ---------------------------------------------------------------------------
// Pre-pass 2: W[K,N] -> Wt[N,K] with bf16 hi/lo split
// ---------------------------------------------------------------------------
__global__ void wsplit_kernel(const float* __restrict__ W0, const float* __restrict__ W1,
                              const float* __restrict__ W2, const float* __restrict__ W3,
                              __nv_bfloat16* __restrict__ hi, __nv_bfloat16* __restrict__ lo)
{
    const int z = blockIdx.z;
    const float* W = (z == 0) ? W0 : (z == 1) ? W1 : (z == 2) ? W2 : W3;
    __shared__ float t[32][33];
    const int n0 = blockIdx.x * 32, k0 = blockIdx.y * 32;
    const int tx = threadIdx.x, ty = threadIdx.y;
#pragma unroll
    for (int i = 0; i < 4; i++)
        t[ty + 8 * i][tx] = W[(size_t)(k0 + ty + 8 * i) * NHD + n0 + tx];
    __syncthreads();
    const size_t zo = (size_t)z * HID * NHD;
#pragma unroll
    for (int i = 0; i < 4; i++) {
        const float x = t[tx][ty + 8 * i];
        const __nv_bfloat16 h = __float2bfloat16(x);
        const __nv_bfloat16 l = __float2bfloat16(x - __bfloat162float(h));
        const size_t o = zo + (size_t)(n0 + ty + 8 * i) * KDIM + k0 + tx;
        hi[o] = h;
        lo[o] = l;
    }
}

// ---------------------------------------------------------------------------
// Split-bf16 HMMA GEMM (identical mainloop to R4; epilogue templated:
// fp32 store or bf16 hi/lo split store)
// ---------------------------------------------------------------------------
#define BK        32
#define NITER     (KDIM / BK)
#define STR_B     80
#define MAT_B     (128 * STR_B)
#define STAGE_B   (4 * MAT_B)
#define GEMM_SMEM (2 * STAGE_B)

struct GemmPtrs {
    const __nv_bfloat16 *Ahi, *Alo, *Bhi, *Blo;
    float* C;
    __nv_bfloat16 *Chi, *Clo;
};

__device__ __forceinline__ void gemm_copy_stage(
    uint32_t sdst, const GemmPtrs& g, int m0, int n0, int kb, int tid)
{
#pragma unroll
    for (int i = 0; i < 8; i++) {
        const int idx = tid + i * 256;
        const int mat = idx >> 9, rem = idx & 511;
        const int row = rem >> 2, c = rem & 3;
        const __nv_bfloat16* sp;
        if (mat == 0)      sp = g.Ahi + (size_t)(m0 + row) * KDIM + kb + c * 8;
        else if (mat == 1) sp = g.Alo + (size_t)(m0 + row) * KDIM + kb + c * 8;
        else if (mat == 2) sp = g.Bhi + (size_t)(n0 + row) * KDIM + kb + c * 8;
        else               sp = g.Blo + (size_t)(n0 + row) * KDIM + kb + c * 8;
        CP_ASYNC16(sdst + mat * MAT_B + row * STR_B + c * 16, sp);
    }
    CP_COMMIT();
}

template <bool SPLIT>
__device__ __forceinline__ void gemm_body_mma(const GemmPtrs& g)
{
    extern __shared__ __align__(128) char smem[];
    const uint32_t sbase = smem_u32(smem);
    const int tid = threadIdx.x, wid = tid >> 5, lane = tid & 31;
    const int m0 = blockIdx.y * 128, n0 = blockIdx.x * 128;
    const int wm = wid & 1, wn = wid >> 1;

    float acc[4][4][4];
#pragma unroll
    for (int a = 0; a < 4; a++)
#pragma unroll
        for (int b = 0; b < 4; b++)
#pragma unroll
            for (int c = 0; c < 4; c++) acc[a][b][c] = 0.f;

    const uint32_t lofs = (uint32_t)((lane & 15) * STR_B + (lane >> 4) * 16);

    gemm_copy_stage(sbase, g, m0, n0, 0, tid);

    for (int t = 0; t < NITER; ++t) {
        if (t + 1 < NITER) {
            gemm_copy_stage(sbase + ((t + 1) & 1) * STAGE_B, g, m0, n0, (t + 1) * BK, tid);
            CP_WAIT(1);
        } else {
            CP_WAIT(0);
        }
        __syncthreads();

        const uint32_t s0 = sbase + (t & 1) * STAGE_B;
#pragma unroll
        for (int ks = 0; ks < 2; ++ks) {
            const uint32_t aoff = s0 + (uint32_t)(wm * 64 * STR_B + ks * 32) + lofs;
            const uint32_t boff = s0 + 2 * MAT_B + (uint32_t)(wn * 32 * STR_B + ks * 32) + lofs;

            uint32_t Ah[16], Bh[8], Bl[8];
            ldm4(Ah + 0,  aoff);
            ldm4(Ah + 4,  aoff + 16 * STR_B);
            ldm4(Ah + 8,  aoff + 32 * STR_B);
            ldm4(Ah + 12, aoff + 48 * STR_B);
            ldm4(Bh + 0, boff);
            ldm4(Bh + 4, boff + 16 * STR_B);
#pragma unroll
            for (int mf = 0; mf < 4; mf++)
#pragma unroll
                for (int nf = 0; nf < 4; nf++)
                    mma_bf16(acc[mf][nf], Ah + mf * 4,
                             Bh[(nf >> 1) * 4 + (nf & 1)], Bh[(nf >> 1) * 4 + 2 + (nf & 1)]);
            ldm4(Bl + 0, boff + MAT_B);
            ldm4(Bl + 4, boff + MAT_B + 16 * STR_B);
#pragma unroll
            for (int mf = 0; mf < 4; mf++)
#pragma unroll
                for (int nf = 0; nf < 4; nf++)
                    mma_bf16(acc[mf][nf], Ah + mf * 4,
                             Bl[(nf >> 1) * 4 + (nf & 1)], Bl[(nf >> 1) * 4 + 2 + (nf & 1)]);
            ldm4(Ah + 0,  aoff + MAT_B);
            ldm4(Ah + 4,  aoff + MAT_B + 16 * STR_B);
            ldm4(Ah + 8,  aoff + MAT_B + 32 * STR_B);
            ldm4(Ah + 12, aoff + MAT_B + 48 * STR_B);
#pragma unroll
            for (int mf = 0; mf < 4; mf++)
#pragma unroll
                for (int nf = 0; nf < 4; nf++)
                    mma_bf16(acc[mf][nf], Ah + mf * 4,
                             Bh[(nf >> 1) * 4 + (nf & 1)], Bh[(nf >> 1) * 4 + 2 + (nf & 1)]);
        }
        __syncthreads();
    }

    const int gq = lane >> 2, tig = lane & 3;
#pragma unroll
    for (int mf = 0; mf < 4; mf++) {
        const int row = m0 + wm * 64 + mf * 16 + gq;
#pragma unroll
        for (int nf = 0; nf < 4; nf++) {
            const int col = n0 + wn * 32 + nf * 8 + tig * 2;
            if (SPLIT) {
#pragma unroll
                for (int half = 0; half < 2; half++) {
                    const size_t off = (size_t)(row + half * 8) * 2048 + col;
                    const float x0 = acc[mf][nf][half * 2], x1 = acc[mf][nf][half * 2 + 1];
                    const __nv_bfloat16 h0 = __float2bfloat16(x0), h1 = __float2bfloat16(x1);
                    const __nv_bfloat16 l0 = __float2bfloat16(x0 - __bfloat162float(h0));
                    const __nv_bfloat16 l1 = __float2bfloat16(x1 - __bfloat162float(h1));
                    *(__nv_bfloat162*)&g.Chi[off] = __nv_bfloat162(h0, h1);
                    *(__nv_bfloat162*)&g.Clo[off] = __nv_bfloat162(l0, l1);
                }
            } else {
                *(float2*)&g.C[(size_t)row * 2048 + col] =
                    make_float2(acc[mf][nf][0], acc[mf][nf][1]);
                *(float2*)&g.C[(size_t)(row + 8) * 2048 + col] =
                    make_float2(acc[mf][nf][2], acc[mf][nf][3]);
            }
        }
    }
}

__global__ __launch_bounds__(256, 2) void qkv_mma_kernel(
    const __nv_bfloat16* __restrict__ Ahi, const __nv_bfloat16* __restrict__ Alo,
    const __nv_bfloat16* __restrict__ Whi, const __nv_bfloat16* __restrict__ Wlo,
    __nv_bfloat16* __restrict__ Qh, __nv_bfloat16* __restrict__ Ql,
    __nv_bfloat16* __restrict__ Kh, __nv_bfloat16* __restrict__ Kl,
    __nv_bfloat16* __restrict__ Vh, __nv_bfloat16* __restrict__ Vl)
{
    const size_t WSZ = (size_t)HID * NHD;
    const int z = blockIdx.z;
    GemmPtrs g;
    g.Ahi = Ahi; g.Alo = Alo;
    g.Bhi = Whi + (size_t)z * WSZ; g.Blo = Wlo + (size_t)z * WSZ;
    g.C = nullptr;
    g.Chi = (z == 0) ? Qh : (z == 1) ? Kh : Vh;
    g.Clo = (z == 0) ? Ql : (z == 1) ? Kl : Vl;
    gemm_body_mma<true>(g);
}

__global__ __launch_bounds__(256, 2) void out_mma_kernel(
    const __nv_bfloat16* __restrict__ Ahi, const __nv_bfloat16* __restrict__ Alo,
    const __nv_bfloat16* __restrict__ Whi, const __nv_bfloat16* __restrict__ Wlo,
    float* __restrict__ C)
{
    GemmPtrs g;
    g.Ahi = Ahi; g.Alo = Alo; g.Bhi = Whi; g.Blo = Wlo;
    g.C = C; g.Chi = nullptr; g.Clo = nullptr;
    gemm_body_mma<false>(g);
}

// ---------------------------------------------------------------------------
// Tensor-core flash attention (split-bf16, 3 products for QK and PV).
// CTA = (tile, head, batch), 8 warps x 16 query rows. Smem: 6 padded tiles.
// ---------------------------------------------------------------------------
#define ASTRB   144                 // 72 bf16 elements per row
#define AQH     0
#define AQL     18432
#define AKH     36864
#define AKL     55296
#define AVH     73728
#define AVL     92160
#define ATT_SMEM 110592

__device__ __forceinline__ int token_of(int tile, int jj)
{
    return ((tile >> 2) << 9) + ((jj >> 4) << 6) + ((tile & 3) << 4) + (jj & 15);
}

__global__ __launch_bounds__(256, 1) void attn_mma_kernel(
    const __nv_bfloat16* __restrict__ Qhi, const __nv_bfloat16* __restrict__ Qlo,
    const __nv_bfloat16* __restrict__ Khi, const __nv_bfloat16* __restrict__ Klo,
    const __nv_bfloat16* __restrict__ Vhi, const __nv_bfloat16* __restrict__ Vlo,
    __nv_bfloat16* __restrict__ Ohi, __nv_bfloat16* __restrict__ Olo)
{
    extern __shared__ __align__(128) char smem[];
    const uint32_t sbase = smem_u32(smem);
    const int t = blockIdx.x, h = blockIdx.y, b = blockIdx.z;
    const int tid = threadIdx.x, w = tid >> 5, lane = tid & 31;
    const size_t base = (size_t)b * S_SZ * NHD + (size_t)h * HD;

    // kv tile window
    const int tr = t >> 2, tc = t & 3;
    const int cr = min(max(tr, 1), 7);
    const int cc = min(max(tc, 1), 3);
    int kts[NKV];
    kts[0] = (cr - 1) * 4 + (cc - 1);
    kts[1] = (cr - 1) * 4 + cc;
    kts[2] = cr * 4 + (cc - 1);
    kts[3] = cr * 4 + cc;

    // Load Q hi/lo tiles (128 rows x 64 dims) into smem
    for (int i = tid; i < 2048; i += 256) {
        const int mat = i >> 10, rem = i & 1023;
        const int row = rem >> 3, c = rem & 7;
        const int qs = token_of(t, row);
        const __nv_bfloat16* src = (mat ? Qlo : Qhi) + base + (size_t)qs * NHD + c * 8;
        CP_ASYNC16(sbase + (mat ? AQL : AQH) + row * ASTRB + c * 16, src);
    }
    CP_COMMIT();
    CP_WAIT(0);
    __syncthreads();

    // Q fragments (warp rows w*16..w*16+15), kept in registers for all tiles
    uint32_t qh[4][4], ql[4][4];
    const uint32_t qoff = (uint32_t)((w * 16 + (lane & 15)) * ASTRB + (lane >> 4) * 16);
#pragma unroll
    for (int kf = 0; kf < 4; kf++) {
        ldm4(qh[kf], sbase + AQH + qoff + kf * 32);
        ldm4(ql[kf], sbase + AQL + qoff + kf * 32);
    }

    float O[8][4];
#pragma unroll
    for (int nf = 0; nf < 8; nf++)
#pragma unroll
        for (int c = 0; c < 4; c++) O[nf][c] = 0.f;
    float m0 = -1e30f, m1 = -1e30f, l0 = 0.f, l1 = 0.f;

    for (int w4 = 0; w4 < NKV; ++w4) {
        const int kt = kts[w4];
        __syncthreads();   // previous tile's K/V consumption complete
        for (int i = tid; i < 4096; i += 256) {
            const int mat = i >> 10, rem = i & 1023;
            const int row = rem >> 3, c = rem & 7;
            const int ks = token_of(kt, row);
            const size_t off = base + (size_t)ks * NHD + c * 8;
            const __nv_bfloat16* src =
                (mat == 0) ? Khi + off : (mat == 1) ? Klo + off :
                (mat == 2) ? Vhi + off : Vlo + off;
            const uint32_t doff = (mat == 0) ? AKH : (mat == 1) ? AKL :
                                  (mat == 2) ? AVH : AVL;
            CP_ASYNC16(sbase + doff + row * ASTRB + c * 16, src);
        }
        CP_COMMIT();
        CP_WAIT(0);
        __syncthreads();

        // ---- S = Q @ K^T (3-product split), 128 keys ----
        float S[16][4];
#pragma unroll
        for (int nf = 0; nf < 16; nf++)
#pragma unroll
            for (int c = 0; c < 4; c++) S[nf][c] = 0.f;

#pragma unroll
        for (int kf = 0; kf < 4; kf++) {
#pragma unroll
            for (int g = 0; g < 8; g++) {
                uint32_t kh[4], kl[4];
                const uint32_t ko = (uint32_t)((g * 16 + (lane & 15)) * ASTRB +
                                               (lane >> 4) * 16 + kf * 32);
                ldm4(kh, sbase + AKH + ko);
                mma_bf16(S[2 * g],     qh[kf], kh[0], kh[2]);
                mma_bf16(S[2 * g + 1], qh[kf], kh[1], kh[3]);
                ldm4(kl, sbase + AKL + ko);
                mma_bf16(S[2 * g],     qh[kf], kl[0], kl[2]);
                mma_bf16(S[2 * g + 1], qh[kf], kl[1], kl[3]);
                mma_bf16(S[2 * g],     ql[kf], kh[0], kh[2]);
                mma_bf16(S[2 * g + 1], ql[kf], kh[1], kh[3]);
            }
        }

        // ---- online softmax on fragments ----
        float tmax0 = -1e30f, tmax1 = -1e30f;
#pragma unroll
        for (int nf = 0; nf < 16; nf++) {
            S[nf][0] *= SCALE_F; S[nf][1] *= SCALE_F;
            S[nf][2] *= SCALE_F; S[nf][3] *= SCALE_F;
            tmax0 = fmaxf(tmax0, fmaxf(S[nf][0], S[nf][1]));
            tmax1 = fmaxf(tmax1, fmaxf(S[nf][2], S[nf][3]));
        }
        tmax0 = fmaxf(tmax0, __shfl_xor_sync(0xFFFFFFFF, tmax0, 1));
        tmax0 = fmaxf(tmax0, __shfl_xor_sync(0xFFFFFFFF, tmax0, 2));
        tmax1 = fmaxf(tmax1, __shfl_xor_sync(0xFFFFFFFF, tmax1, 1));
        tmax1 = fmaxf(tmax1, __shfl_xor_sync(0xFFFFFFFF, tmax1, 2));

        const float mn0 = fmaxf(m0, tmax0), mn1 = fmaxf(m1, tmax1);
        const float a0 = __expf(m0 - mn0), a1 = __expf(m1 - mn1);
        m0 = mn0; m1 = mn1;
        l0 *= a0; l1 *= a1;
#pragma unroll
        for (int nf = 0; nf < 8; nf++) {
            O[nf][0] *= a0; O[nf][1] *= a0;
            O[nf][2] *= a1; O[nf][3] *= a1;
        }
        float ls0 = 0.f, ls1 = 0.f;
#pragma unroll
        for (int nf = 0; nf < 16; nf++) {
            S[nf][0] = __expf(S[nf][0] - m0); ls0 += S[nf][0];
            S[nf][1] = __expf(S[nf][1] - m0); ls0 += S[nf][1];
            S[nf][2] = __expf(S[nf][2] - m1); ls1 += S[nf][2];
            S[nf][3] = __expf(S[nf][3] - m1); ls1 += S[nf][3];
        }
        l0 += ls0; l1 += ls1;

        // ---- O += P @ V (3-product split); P frags direct from S regs ----
#pragma unroll
        for (int kf = 0; kf < 8; kf++) {
            uint32_t ph[4], pl[4];
            {
                const float* sA = S[2 * kf];
                const float* sB = S[2 * kf + 1];
                float hA0 = __bfloat162float(__float2bfloat16(sA[0]));
                float hA1 = __bfloat162float(__float2bfloat16(sA[1]));
                float hA2 = __bfloat162float(__float2bfloat16(sA[2]));
                float hA3 = __bfloat162float(__float2bfloat16(sA[3]));
                float hB0 = __bfloat162float(__float2bfloat16(sB[0]));
                float hB1 = __bfloat162float(__float2bfloat16(sB[1]));
                float hB2 = __bfloat162float(__float2bfloat16(sB[2]));
                float hB3 = __bfloat162float(__float2bfloat16(sB[3]));
                ph[0] = pkbf(sA[0], sA[1]); pl[0] = pkbf(sA[0] - hA0, sA[1] - hA1);
                ph[1] = pkbf(sA[2], sA[3]); pl[1] = pkbf(sA[2] - hA2, sA[3] - hA3);
                ph[2] = pkbf(sB[0], sB[1]); pl[2] = pkbf(sB[0] - hB0, sB[1] - hB1);
                ph[3] = pkbf(sB[2], sB[3]); pl[3] = pkbf(sB[2] - hB2, sB[3] - hB3);
            }
#pragma unroll
            for (int nv = 0; nv < 4; nv++) {
                uint32_t vh[4], vl[4];
                const uint32_t vo = (uint32_t)((kf * 16 + (lane & 15)) * ASTRB +
                                               (lane >> 4) * 16 + nv * 32);
                ldm4t(vh, sbase + AVH + vo);
                mma_bf16(O[2 * nv],     ph, vh[0], vh[1]);
                mma_bf16(O[2 * nv + 1], ph, vh[2], vh[3]);
                ldm4t(vl, sbase + AVL + vo);
                mma_bf16(O[2 * nv],     ph, vl[0], vl[1]);
                mma_bf16(O[2 * nv + 1], ph, vl[2], vl[3]);
                mma_bf16(O[2 * nv],     pl, vh[0], vh[1]);
                mma_bf16(O[2 * nv + 1], pl, vh[2], vh[3]);
            }
        }
    }

    // ---- epilogue: normalize, split hi/lo, store ----
    l0 += __shfl_xor_sync(0xFFFFFFFF, l0, 1);
    l0 += __shfl_xor_sync(0xFFFFFFFF, l0, 2);
    l1 += __shfl_xor_sync(0xFFFFFFFF, l1, 1);
    l1 += __shfl_xor_sync(0xFFFFFFFF, l1, 2);
    const float inv0 = 1.f / l0, inv1 = 1.f / l1;
    const int gq = lane >> 2, tig = lane & 3;
    const int qs0 = token_of(t, w * 16 + gq);
    const int qs1 = token_of(t, w * 16 + gq + 8);
    const size_t r0 = base + (size_t)qs0 * NHD;
    const size_t r1 = base + (size_t)qs1 * NHD;
#pragma unroll
    for (int nf = 0; nf < 8; nf++) {
        const int col = nf * 8 + tig * 2;
        const float x0 = O[nf][0] * inv0, x1 = O[nf][1] * inv0;
        const float x2 = O[nf][2] * inv1, x3 = O[nf][3] * inv1;
        const __nv_bfloat16 h0 = __float2bfloat16(x0), h1 = __float2bfloat16(x1);
        const __nv_bfloat16 h2 = __float2bfloat16(x2), h3 = __float2bfloat16(x3);
        *(__nv_bfloat162*)&Ohi[r0 + col] = __nv_bfloat162(h0, h1);
        *(__nv_bfloat162*)&Ohi[r1 + col] = __nv_bfloat162(h2, h3);
        *(__nv_bfloat162*)&Olo[r0 + col] = __nv_bfloat162(
            __float2bfloat16(x0 - __bfloat162float(h0)),
            __float2bfloat16(x1 - __bfloat162float(h1)));
        *(__nv_bfloat162*)&Olo[r1 + col] = __nv_bfloat162(
            __float2bfloat16(x2 - __bfloat162float(h2)),
            __float2bfloat16(x3 - __bfloat162float(h3)));
    }
}

// ---------------------------------------------------------------------------
// Launch
// ---------------------------------------------------------------------------
extern "C" void kernel_launch(void* const* d_in, const int* in_sizes, int n_in,
                              void* d_out, int out_size)
{
    const float* hs = (const float*)d_in[0];
    const float* Wq = (const float*)d_in[1];
    const float* Wk = (const float*)d_in[2];
    const float* Wv = (const float*)d_in[3];
    const float* Wo = (const float*)d_in[4];
    float* out = (float*)d_out;

    __nv_bfloat16 *hshi, *hslo, *wthi, *wtlo;
    __nv_bfloat16 *qhi, *qlo, *khi, *klo, *vhi, *vlo, *atthi, *attlo;
    cudaGetSymbolAddress((void**)&hshi, g_hshi);
    cudaGetSymbolAddress((void**)&hslo, g_hslo);
    cudaGetSymbolAddress((void**)&wthi, g_wthi);
    cudaGetSymbolAddress((void**)&wtlo, g_wtlo);
    cudaGetSymbolAddress((void**)&qhi, g_qhi);
    cudaGetSymbolAddress((void**)&qlo, g_qlo);
    cudaGetSymbolAddress((void**)&khi, g_khi);
    cudaGetSymbolAddress((void**)&klo, g_klo);
    cudaGetSymbolAddress((void**)&vhi, g_vhi);
    cudaGetSymbolAddress((void**)&vlo, g_vlo);
    cudaGetSymbolAddress((void**)&atthi, g_atthi);
    cudaGetSymbolAddress((void**)&attlo, g_attlo);

    cudaFuncSetAttribute(qkv_mma_kernel, cudaFuncAttributeMaxDynamicSharedMemorySize, GEMM_SMEM);
    cudaFuncSetAttribute(out_mma_kernel, cudaFuncAttributeMaxDynamicSharedMemorySize, GEMM_SMEM);
    cudaFuncSetAttribute(attn_mma_kernel, cudaFuncAttributeMaxDynamicSharedMemorySize, ATT_SMEM);

    const int n4 = (M_ROWS * HID) / 4;
    split_kernel<<<(n4 + 255) / 256, 256>>>(hs, hshi, hslo, n4);
    wsplit_kernel<<<dim3(NHD / 32, HID / 32, 4), dim3(32, 8)>>>(Wq, Wk, Wv, Wo, wthi, wtlo);

    qkv_mma_kernel<<<dim3(NHD / 128, M_ROWS / 128, 3), 256, GEMM_SMEM>>>(
        hshi, hslo, wthi, wtlo, qhi, qlo, khi, klo, vhi, vlo);

    attn_mma_kernel<<<dim3(NT, NH, B_SZ), 256, ATT_SMEM>>>(
        qhi, qlo, khi, klo, vhi, vlo, atthi, attlo);

    const size_t WSZ = (size_t)HID * NHD;
    out_mma_kernel<<<dim3(HID / 128, M_ROWS / 128), 256, GEMM_SMEM>>>(
        atthi, attlo, wthi + 3 * WSZ, wtlo + 3 * WSZ, out);
}